// round 7
// baseline (speedup 1.0000x reference)
#include <cuda_runtime.h>
#include <math.h>

#define DIMV   512
#define C_NUM  16
#define ALPHA_C 0.1f
#define BETA_C  1.1f
#define EPS_C   1e-8f
#define K2_BLOCKS 256
#define XSTRIDE 68   // 64-dim chunk padded: (4n + d) % 32 bank pattern, conflict-free LDS.128

// ------------------- static device scratch (no allocations allowed) -------------------
__device__ float g_part[K2_BLOCKS * C_NUM * DIMV];   // per-block partial class sums (8 MB)
__device__ int   g_cntpart[K2_BLOCKS * C_NUM];       // per-block class counts
__device__ float g_cnT[DIMV * C_NUM];                // normalized centroids, transposed [d][c]
__device__ float g_cntf[C_NUM];                      // class counts (float)
__device__ float g_deg[C_NUM];                       // pairs involving each class
__device__ float g_pm[C_NUM * C_NUM];                // pair mask
__device__ float g_S[C_NUM * C_NUM];                 // S[c][c'] accumulator
__device__ float g_intra;
__device__ float g_count;
__device__ float g_numpairs;

// ------------------- K1: zero global accumulators -------------------
__global__ void k_init() {
    int i = threadIdx.x;
    if (i < C_NUM * C_NUM) g_S[i] = 0.f;
    if (i == 0) g_intra = 0.f;
}

// ------------------- K2: per-block class sums (race-free shared accumulation) ------------
// Thread t exclusively owns dims {2t, 2t+1} of every class row -> no atomics needed.
__global__ __launch_bounds__(256) void k_sums(const float* __restrict__ emb,
                                              const int* __restrict__ labels, int n) {
    __shared__ float acc[C_NUM * DIMV];   // 32 KB
    __shared__ int   scnt[C_NUM];
    int t = threadIdx.x;
    #pragma unroll
    for (int c = 0; c < C_NUM; c++) {
        acc[c * DIMV + 2 * t]     = 0.f;
        acc[c * DIMV + 2 * t + 1] = 0.f;
    }
    if (t < C_NUM) scnt[t] = 0;
    __syncthreads();

    #pragma unroll 4
    for (int r = blockIdx.x; r < n; r += K2_BLOCKS) {
        int lbl = __ldg(&labels[r]);                       // uniform broadcast load
        float2 v = *(const float2*)(emb + (size_t)r * DIMV + 2 * t);
        float2 a = *(float2*)&acc[lbl * DIMV + 2 * t];
        a.x += v.x; a.y += v.y;
        *(float2*)&acc[lbl * DIMV + 2 * t] = a;
        if (t == 0) scnt[lbl]++;
    }
    __syncthreads();

    float* dst = g_part + (size_t)blockIdx.x * (C_NUM * DIMV);
    for (int i = t; i < C_NUM * DIMV; i += 256) dst[i] = acc[i];
    if (t < C_NUM) g_cntpart[blockIdx.x * C_NUM + t] = scnt[t];
}

// ------------------- K3: reduce partials -> normalized centroids (one block per class) ---
__global__ __launch_bounds__(256) void k_centroid() {
    int c = blockIdx.x;   // 0..15
    int t = threadIdx.x;  // 0..255
    __shared__ float sred[8];
    __shared__ float s_cf, s_inv;

    // count reduction: thread t reads partial-block t's count for class c
    float myc = (float)g_cntpart[t * C_NUM + c];
    #pragma unroll
    for (int o = 16; o > 0; o >>= 1) myc += __shfl_down_sync(0xFFFFFFFFu, myc, o);
    if ((t & 31) == 0) sred[t >> 5] = myc;
    __syncthreads();
    if (t == 0) {
        float cf = 0.f;
        #pragma unroll
        for (int w = 0; w < 8; w++) cf += sred[w];
        s_cf = cf;
        g_cntf[c] = cf;
    }
    __syncthreads();
    float mx = fmaxf(s_cf, 1.f);

    // sum partials for my two dims (t, t+256)
    float s0 = 0.f, s1 = 0.f;
    const float* p = g_part + c * DIMV;
    #pragma unroll 4
    for (int b = 0; b < K2_BLOCKS; b++) {
        s0 += p[(size_t)b * (C_NUM * DIMV) + t];
        s1 += p[(size_t)b * (C_NUM * DIMV) + t + 256];
    }
    float c0 = s0 / mx, c1 = s1 / mx;

    // norm reduction
    float sq = c0 * c0 + c1 * c1;
    #pragma unroll
    for (int o = 16; o > 0; o >>= 1) sq += __shfl_down_sync(0xFFFFFFFFu, sq, o);
    __syncthreads();   // protect sred reuse
    if ((t & 31) == 0) sred[t >> 5] = sq;
    __syncthreads();
    if (t == 0) {
        float ns = 0.f;
        #pragma unroll
        for (int w = 0; w < 8; w++) ns += sred[w];
        s_inv = 1.f / fmaxf(sqrtf(ns), EPS_C);
    }
    __syncthreads();
    float inv = s_inv;
    g_cnT[t * C_NUM + c]         = c0 * inv;   // transposed layout [d][c]
    g_cnT[(t + 256) * C_NUM + c] = c1 * inv;
}

// ------------------- K3b: centroid pair analysis (single block) -------------------
__global__ void k_pairs() {
    int t = threadIdx.x;           // 256 threads = 16x16 pairs
    int i = t >> 4, j = t & 15;
    float dot = 0.f;
    #pragma unroll 8
    for (int d = 0; d < DIMV; d++)
        dot += __ldg(&g_cnT[d * C_NUM + i]) * __ldg(&g_cnT[d * C_NUM + j]);
    float pd = 1.f - dot;
    float ci = g_cntf[i], cj = g_cntf[j];
    float pm = (i < j && ci > 0.f && cj > 0.f && pd <= BETA_C) ? 1.f : 0.f;

    __shared__ float spm[256];
    __shared__ float sdeg[16];
    spm[t] = pm;
    g_pm[t] = pm;
    __syncthreads();
    if (t < 16) {
        float dg = 0.f;
        #pragma unroll
        for (int k = 0; k < 16; k++) dg += spm[t * 16 + k] + spm[k * 16 + t];
        sdeg[t] = dg;
        g_deg[t] = dg;
    }
    __syncthreads();
    if (t == 0) {
        float cnt_total = 0.f, np = 0.f;
        #pragma unroll
        for (int c = 0; c < 16; c++) cnt_total += sdeg[c] * g_cntf[c];
        for (int k = 0; k < 256; k++) np += spm[k];
        g_count = cnt_total;
        g_numpairs = np;
    }
}

// ------------------- K4: main pass — dots to all 16 centroids + fused epilogue -----------
__global__ __launch_bounds__(256) void k_pass2(const float* __restrict__ emb,
                                               const int* __restrict__ labels, int n) {
    extern __shared__ float sh[];
    float* s_x   = sh;                          // [256][XSTRIDE]
    float* s_c   = s_x + 256 * XSTRIDE;         // [512][16] centroids transposed
    float* s_S   = s_c + DIMV * C_NUM;          // [16][16]
    float* s_red = s_S + C_NUM * C_NUM;         // [8]

    int t = threadIdx.x;
    for (int i = t; i < DIMV * C_NUM; i += 256) s_c[i] = g_cnT[i];
    s_S[t] = 0.f;

    int row0 = blockIdx.x * 256;
    int myrow = row0 + t;
    bool valid = (myrow < n);

    float acc[16];
    #pragma unroll
    for (int c = 0; c < 16; c++) acc[c] = 0.f;
    float nrm = 0.f;

    for (int ch = 0; ch < DIMV; ch += 64) {
        __syncthreads();   // also covers s_c/s_S init on first iter
        // stage [256 rows][64 dims] tile, fully coalesced float4 loads
        #pragma unroll
        for (int k = 0; k < 16; k++) {
            int idx = k * 256 + t;
            int rr = idx >> 4;
            int q  = idx & 15;
            int grow = row0 + rr;
            float4 v = make_float4(0.f, 0.f, 0.f, 0.f);
            if (grow < n) v = *(const float4*)(emb + (size_t)grow * DIMV + ch + q * 4);
            *(float4*)&s_x[rr * XSTRIDE + q * 4] = v;
        }
        __syncthreads();

        const float* xp = &s_x[t * XSTRIDE];
        #pragma unroll 4
        for (int d4 = 0; d4 < 64; d4 += 4) {
            float4 xv = *(const float4*)(xp + d4);
            nrm += xv.x * xv.x; nrm += xv.y * xv.y;
            nrm += xv.z * xv.z; nrm += xv.w * xv.w;
            const float* cb = &s_c[(ch + d4) * C_NUM];
            #pragma unroll
            for (int dd = 0; dd < 4; dd++) {
                float xs = (&xv.x)[dd];
                #pragma unroll
                for (int c4 = 0; c4 < 4; c4++) {
                    float4 cv = *(const float4*)(cb + dd * C_NUM + c4 * 4);  // broadcast
                    acc[c4 * 4 + 0] += xs * cv.x;
                    acc[c4 * 4 + 1] += xs * cv.y;
                    acc[c4 * 4 + 2] += xs * cv.z;
                    acc[c4 * 4 + 3] += xs * cv.w;
                }
            }
        }
    }

    // epilogue: D[c] = 1 - cn[c]·xn ; fold into intra & S
    float intra_part = 0.f;
    if (valid) {
        int lbl = __ldg(&labels[myrow]);
        float inv = 1.f / fmaxf(sqrtf(nrm), EPS_C);
        float down = 0.f;
        #pragma unroll
        for (int c = 0; c < 16; c++) {
            float D = 1.f - acc[c] * inv;
            float s = BETA_C - D;
            if (s > 0.f) atomicAdd(&s_S[c * 16 + lbl], s);
            if (c == lbl) down = D;
        }
        intra_part = __ldg(&g_deg[lbl]) * fmaxf(down - ALPHA_C, 0.f);
    }

    // block reduce intra, then flush
    #pragma unroll
    for (int o = 16; o > 0; o >>= 1)
        intra_part += __shfl_down_sync(0xFFFFFFFFu, intra_part, o);
    if ((t & 31) == 0) s_red[t >> 5] = intra_part;
    __syncthreads();   // also orders s_S shared atomics before the flush below
    if (t == 0) {
        float v = 0.f;
        #pragma unroll
        for (int w = 0; w < 8; w++) v += s_red[w];
        atomicAdd(&g_intra, v);
    }
    atomicAdd(&g_S[t], s_S[t]);   // t covers all 256 = 16x16 cells
}

// ------------------- K5: final scalar -------------------
__global__ void k_final(float* __restrict__ out) {
    int t = threadIdx.x;   // 256
    __shared__ float sred[8];
    int i = t >> 4, j = t & 15;
    float v = g_pm[t] * (g_S[t] + g_S[j * 16 + i]);
    #pragma unroll
    for (int o = 16; o > 0; o >>= 1) v += __shfl_down_sync(0xFFFFFFFFu, v, o);
    if ((t & 31) == 0) sred[t >> 5] = v;
    __syncthreads();
    if (t == 0) {
        float inter = 0.f;
        #pragma unroll
        for (int w = 0; w < 8; w++) inter += sred[w];
        float denom = fmaxf(g_count, 1.f);
        out[0] = (g_numpairs > 0.f) ? (g_intra + inter) / denom : 0.f;
    }
}

// ------------------- launch -------------------
extern "C" void kernel_launch(void* const* d_in, const int* in_sizes, int n_in,
                              void* d_out, int out_size) {
    const float* emb    = (const float*)d_in[0];
    const int*   labels = (const int*)d_in[1];
    int n = in_sizes[1];   // number of samples (labels count)

    int smem = (256 * XSTRIDE + DIMV * C_NUM + C_NUM * C_NUM + 8) * (int)sizeof(float);
    cudaFuncSetAttribute(k_pass2, cudaFuncAttributeMaxDynamicSharedMemorySize, smem);

    k_init<<<1, 256>>>();
    k_sums<<<K2_BLOCKS, 256>>>(emb, labels, n);
    k_centroid<<<C_NUM, 256>>>();
    k_pairs<<<1, 256>>>();
    int blocks = (n + 255) / 256;
    k_pass2<<<blocks, 256, smem>>>(emb, labels, n);
    k_final<<<1, 256>>>((float*)d_out);
}

// round 8
// speedup vs baseline: 1.1240x; 1.1240x over previous
#include <cuda_runtime.h>
#include <math.h>

#define DIMV   512
#define C_NUM  16
#define ALPHA_C 0.1f
#define BETA_C  1.1f
#define EPS_C   1e-8f
#define K2_BLOCKS 256
#define XSTRIDE 68   // 64-dim chunk padded: conflict-free LDS.128

// ------------------- static device scratch (no allocations allowed) -------------------
__device__ float g_sums[C_NUM * DIMV];               // global class sums (atomic target)
__device__ int   g_cnt[C_NUM];                       // class counts (atomic target)
__device__ float g_cnT[DIMV * C_NUM];                // normalized centroids, transposed [d][c]
__device__ float g_cntf[C_NUM];                      // class counts (float)
__device__ float g_deg[C_NUM];                       // pairs involving each class
__device__ float g_pm[C_NUM * C_NUM];                // pair mask
__device__ float g_S[C_NUM * C_NUM];                 // S[c][c'] accumulator
__device__ float g_intra;
__device__ float g_count;
__device__ float g_numpairs;

// packed f32x2 FFMA (ptxas never emits FFMA2 from C++; PTX-only path)
__device__ __forceinline__ void ffma2(unsigned long long& d,
                                      unsigned long long a, unsigned long long b) {
    asm("fma.rn.f32x2 %0, %1, %2, %0;" : "+l"(d) : "l"(a), "l"(b));
}
__device__ __forceinline__ unsigned long long pack2(float lo, float hi) {
    unsigned long long r;
    asm("mov.b64 %0, {%1, %2};" : "=l"(r) : "f"(lo), "f"(hi));
    return r;
}

// ------------------- K1: zero global accumulators -------------------
__global__ void k_init() {
    int i = blockIdx.x * blockDim.x + threadIdx.x;
    if (i < C_NUM * DIMV) g_sums[i] = 0.f;
    if (i < C_NUM) g_cnt[i] = 0;
    if (i < C_NUM * C_NUM) g_S[i] = 0.f;
    if (i == 0) g_intra = 0.f;
}

// ------------------- K2: class sums (race-free shared accumulation, atomic flush) --------
// Thread t exclusively owns dims {2t, 2t+1} of every class row -> no atomics in the loop.
__global__ __launch_bounds__(256) void k_sums(const float* __restrict__ emb,
                                              const int* __restrict__ labels, int n) {
    __shared__ float acc[C_NUM * DIMV];   // 32 KB
    __shared__ int   scnt[C_NUM];
    int t = threadIdx.x;
    #pragma unroll
    for (int c = 0; c < C_NUM; c++) {
        acc[c * DIMV + 2 * t]     = 0.f;
        acc[c * DIMV + 2 * t + 1] = 0.f;
    }
    if (t < C_NUM) scnt[t] = 0;
    __syncthreads();

    #pragma unroll 4
    for (int r = blockIdx.x; r < n; r += K2_BLOCKS) {
        int lbl = __ldg(&labels[r]);                       // uniform broadcast load
        float2 v = *(const float2*)(emb + (size_t)r * DIMV + 2 * t);
        float2 a = *(float2*)&acc[lbl * DIMV + 2 * t];
        a.x += v.x; a.y += v.y;
        *(float2*)&acc[lbl * DIMV + 2 * t] = a;
        if (t == 0) scnt[lbl]++;
    }
    __syncthreads();

    for (int i = t; i < C_NUM * DIMV; i += 256) atomicAdd(&g_sums[i], acc[i]);
    if (t < C_NUM) atomicAdd(&g_cnt[t], scnt[t]);
}

// ------------------- K3: normalize centroids (one block per class, tiny) -------------------
__global__ __launch_bounds__(256) void k_centroid() {
    int c = blockIdx.x;   // 0..15
    int t = threadIdx.x;  // 0..255
    __shared__ float sred[8];
    __shared__ float s_inv;

    float cf = (float)g_cnt[c];
    float mx = fmaxf(cf, 1.f);
    float c0 = g_sums[c * DIMV + t] / mx;
    float c1 = g_sums[c * DIMV + t + 256] / mx;

    float sq = c0 * c0 + c1 * c1;
    #pragma unroll
    for (int o = 16; o > 0; o >>= 1) sq += __shfl_down_sync(0xFFFFFFFFu, sq, o);
    if ((t & 31) == 0) sred[t >> 5] = sq;
    __syncthreads();
    if (t == 0) {
        float ns = 0.f;
        #pragma unroll
        for (int w = 0; w < 8; w++) ns += sred[w];
        s_inv = 1.f / fmaxf(sqrtf(ns), EPS_C);
        g_cntf[c] = cf;
    }
    __syncthreads();
    float inv = s_inv;
    g_cnT[t * C_NUM + c]         = c0 * inv;   // transposed layout [d][c]
    g_cnT[(t + 256) * C_NUM + c] = c1 * inv;
}

// ------------------- K3b: centroid pair analysis (single block, smem-staged) -------------
__global__ __launch_bounds__(256) void k_pairs() {
    __shared__ float sc[DIMV * C_NUM];   // 32 KB staged centroids
    int t = threadIdx.x;                 // 256 threads = 16x16 pairs
    #pragma unroll
    for (int k = 0; k < 8; k++)
        *(float4*)&sc[(k * 256 + t) * 4] = *(const float4*)&g_cnT[(k * 256 + t) * 4];
    __syncthreads();

    int i = t >> 4, j = t & 15;
    float dot = 0.f;
    #pragma unroll 8
    for (int d = 0; d < DIMV; d++)
        dot += sc[d * C_NUM + i] * sc[d * C_NUM + j];
    float pd = 1.f - dot;
    float ci = g_cntf[i], cj = g_cntf[j];
    float pm = (i < j && ci > 0.f && cj > 0.f && pd <= BETA_C) ? 1.f : 0.f;

    __shared__ float spm[256];
    __shared__ float sdeg[16];
    spm[t] = pm;
    g_pm[t] = pm;
    __syncthreads();
    if (t < 16) {
        float dg = 0.f;
        #pragma unroll
        for (int k = 0; k < 16; k++) dg += spm[t * 16 + k] + spm[k * 16 + t];
        sdeg[t] = dg;
        g_deg[t] = dg;
    }
    __syncthreads();
    if (t == 0) {
        float cnt_total = 0.f, np = 0.f;
        #pragma unroll
        for (int c = 0; c < 16; c++) cnt_total += sdeg[c] * g_cntf[c];
        for (int k = 0; k < 256; k++) np += spm[k];
        g_count = cnt_total;
        g_numpairs = np;
    }
}

// ------------------- K4: main pass — packed-f32x2 dots to 16 centroids + fused epilogue --
__global__ __launch_bounds__(256) void k_pass2(const float* __restrict__ emb,
                                               const int* __restrict__ labels, int n) {
    extern __shared__ float sh[];
    float* s_x   = sh;                          // [256][XSTRIDE]
    float* s_c   = s_x + 256 * XSTRIDE;         // [512][16] centroids transposed
    float* s_S   = s_c + DIMV * C_NUM;          // [16][16]
    float* s_red = s_S + C_NUM * C_NUM;         // [8]

    int t = threadIdx.x;
    for (int i = t; i < DIMV * C_NUM; i += 256) s_c[i] = g_cnT[i];
    s_S[t] = 0.f;

    int row0 = blockIdx.x * 256;
    int myrow = row0 + t;
    bool valid = (myrow < n);

    unsigned long long acc2[8];                 // 16 packed class accumulators
    #pragma unroll
    for (int c8 = 0; c8 < 8; c8++) acc2[c8] = 0ull;   // bit pattern = {+0.f, +0.f}
    unsigned long long nrm2 = 0ull;

    for (int ch = 0; ch < DIMV; ch += 64) {
        __syncthreads();   // also covers s_c/s_S init on first iter
        // stage [256 rows][64 dims] tile, fully coalesced float4 loads
        #pragma unroll
        for (int k = 0; k < 16; k++) {
            int idx = k * 256 + t;
            int rr = idx >> 4;
            int q  = idx & 15;
            int grow = row0 + rr;
            float4 v = make_float4(0.f, 0.f, 0.f, 0.f);
            if (grow < n) v = *(const float4*)(emb + (size_t)grow * DIMV + ch + q * 4);
            *(float4*)&s_x[rr * XSTRIDE + q * 4] = v;
        }
        __syncthreads();

        const float* xp = &s_x[t * XSTRIDE];
        #pragma unroll 4
        for (int d4 = 0; d4 < 64; d4 += 4) {
            float4 xv = *(const float4*)(xp + d4);
            unsigned long long xy = pack2(xv.x, xv.y);
            unsigned long long zw = pack2(xv.z, xv.w);
            ffma2(nrm2, xy, xy);
            ffma2(nrm2, zw, zw);
            const float* cb = &s_c[(ch + d4) * C_NUM];
            #pragma unroll
            for (int dd = 0; dd < 4; dd++) {
                unsigned long long xs2 = pack2((&xv.x)[dd], (&xv.x)[dd]);
                #pragma unroll
                for (int c4 = 0; c4 < 4; c4++) {
                    // classes c4*4 .. c4*4+3 for this dim: one LDS.128 -> two f32x2
                    ulonglong2 cv = *(const ulonglong2*)(cb + dd * C_NUM + c4 * 4);
                    ffma2(acc2[c4 * 2 + 0], xs2, cv.x);
                    ffma2(acc2[c4 * 2 + 1], xs2, cv.y);
                }
            }
        }
    }

    // unpack packed accumulators
    float accf[16];
    #pragma unroll
    for (int c8 = 0; c8 < 8; c8++)
        asm("mov.b64 {%0, %1}, %2;" : "=f"(accf[2 * c8]), "=f"(accf[2 * c8 + 1]) : "l"(acc2[c8]));
    float nlo, nhi;
    asm("mov.b64 {%0, %1}, %2;" : "=f"(nlo), "=f"(nhi) : "l"(nrm2));
    float nrm = nlo + nhi;

    // epilogue: D[c] = 1 - cn[c]·xn ; fold into intra & S
    float intra_part = 0.f;
    if (valid) {
        int lbl = __ldg(&labels[myrow]);
        float inv = 1.f / fmaxf(sqrtf(nrm), EPS_C);
        float down = 0.f;
        #pragma unroll
        for (int c = 0; c < 16; c++) {
            float D = 1.f - accf[c] * inv;
            float s = BETA_C - D;
            if (s > 0.f) atomicAdd(&s_S[c * 16 + lbl], s);
            if (c == lbl) down = D;
        }
        intra_part = __ldg(&g_deg[lbl]) * fmaxf(down - ALPHA_C, 0.f);
    }

    // block reduce intra, then flush
    #pragma unroll
    for (int o = 16; o > 0; o >>= 1)
        intra_part += __shfl_down_sync(0xFFFFFFFFu, intra_part, o);
    if ((t & 31) == 0) s_red[t >> 5] = intra_part;
    __syncthreads();   // also orders s_S shared atomics before the flush below
    if (t == 0) {
        float v = 0.f;
        #pragma unroll
        for (int w = 0; w < 8; w++) v += s_red[w];
        atomicAdd(&g_intra, v);
    }
    atomicAdd(&g_S[t], s_S[t]);   // t covers all 256 = 16x16 cells
}

// ------------------- K5: final scalar -------------------
__global__ void k_final(float* __restrict__ out) {
    int t = threadIdx.x;   // 256
    __shared__ float sred[8];
    int i = t >> 4, j = t & 15;
    float v = g_pm[t] * (g_S[t] + g_S[j * 16 + i]);
    #pragma unroll
    for (int o = 16; o > 0; o >>= 1) v += __shfl_down_sync(0xFFFFFFFFu, v, o);
    if ((t & 31) == 0) sred[t >> 5] = v;
    __syncthreads();
    if (t == 0) {
        float inter = 0.f;
        #pragma unroll
        for (int w = 0; w < 8; w++) inter += sred[w];
        float denom = fmaxf(g_count, 1.f);
        out[0] = (g_numpairs > 0.f) ? (g_intra + inter) / denom : 0.f;
    }
}

// ------------------- launch -------------------
extern "C" void kernel_launch(void* const* d_in, const int* in_sizes, int n_in,
                              void* d_out, int out_size) {
    const float* emb    = (const float*)d_in[0];
    const int*   labels = (const int*)d_in[1];
    int n = in_sizes[1];   // number of samples (labels count)

    int smem = (256 * XSTRIDE + DIMV * C_NUM + C_NUM * C_NUM + 8) * (int)sizeof(float);
    cudaFuncSetAttribute(k_pass2, cudaFuncAttributeMaxDynamicSharedMemorySize, smem);

    k_init<<<32, 256>>>();
    k_sums<<<K2_BLOCKS, 256>>>(emb, labels, n);
    k_centroid<<<C_NUM, 256>>>();
    k_pairs<<<1, 256>>>();
    int blocks = (n + 255) / 256;
    k_pass2<<<blocks, 256, smem>>>(emb, labels, n);
    k_final<<<1, 256>>>((float*)d_out);
}

// round 11
// speedup vs baseline: 1.2984x; 1.1552x over previous
#include <cuda_runtime.h>
#include <math.h>

#define DIMV   512
#define C_NUM  16
#define ALPHA_C 0.1f
#define BETA_C  1.1f
#define EPS_C   1e-8f
#define K2_BLOCKS 256
#define P2_THREADS 128
#define P2_R 4           // samples per thread
#define P2_ROWS (P2_THREADS * P2_R)   // 512 rows per block
#define PSTRIDE 516      // k_pairs padded row stride (516 % 32 == 4 -> conflict-free LDS.128)

// ------------------- static device scratch (no allocations allowed) -------------------
__device__ float g_sums[C_NUM * DIMV];               // global class sums (atomic target)
__device__ int   g_cnt[C_NUM];                       // class counts (atomic target)
__device__ float g_cnT[DIMV * C_NUM];                // normalized centroids, transposed [d][c]
__device__ float g_cnC[C_NUM * DIMV];                // normalized centroids, row-major [c][d]
__device__ float g_cntf[C_NUM];                      // class counts (float)
__device__ float g_deg[C_NUM];                       // pairs involving each class
__device__ float g_pm[C_NUM * C_NUM];                // pair mask
__device__ float g_S[C_NUM * C_NUM];                 // S[c][c'] accumulator
__device__ float g_intra;
__device__ float g_count;
__device__ float g_numpairs;

// packed f32x2 FFMA (ptxas never emits FFMA2 from C++; PTX-only path)
__device__ __forceinline__ void ffma2(unsigned long long& d,
                                      unsigned long long a, unsigned long long b) {
    asm("fma.rn.f32x2 %0, %1, %2, %0;" : "+l"(d) : "l"(a), "l"(b));
}
__device__ __forceinline__ unsigned long long pack2(float lo, float hi) {
    unsigned long long r;
    asm("mov.b64 %0, {%1, %2};" : "=l"(r) : "f"(lo), "f"(hi));
    return r;
}

// ------------------- K1: zero global accumulators -------------------
__global__ void k_init() {
    int i = blockIdx.x * blockDim.x + threadIdx.x;
    if (i < C_NUM * DIMV) g_sums[i] = 0.f;
    if (i < C_NUM) g_cnt[i] = 0;
    if (i < C_NUM * C_NUM) g_S[i] = 0.f;
    if (i == 0) g_intra = 0.f;
}

// ------------------- K2: class sums (race-free shared accumulation, atomic flush) --------
// Thread t exclusively owns dims {2t, 2t+1} of every class row -> no atomics in the loop.
__global__ __launch_bounds__(256) void k_sums(const float* __restrict__ emb,
                                              const int* __restrict__ labels, int n) {
    __shared__ float acc[C_NUM * DIMV];   // 32 KB
    __shared__ int   scnt[C_NUM];
    int t = threadIdx.x;
    #pragma unroll
    for (int c = 0; c < C_NUM; c++) {
        acc[c * DIMV + 2 * t]     = 0.f;
        acc[c * DIMV + 2 * t + 1] = 0.f;
    }
    if (t < C_NUM) scnt[t] = 0;
    __syncthreads();

    #pragma unroll 4
    for (int r = blockIdx.x; r < n; r += K2_BLOCKS) {
        int lbl = __ldg(&labels[r]);                       // uniform broadcast load
        float2 v = *(const float2*)(emb + (size_t)r * DIMV + 2 * t);
        float2 a = *(float2*)&acc[lbl * DIMV + 2 * t];
        a.x += v.x; a.y += v.y;
        *(float2*)&acc[lbl * DIMV + 2 * t] = a;
        if (t == 0) scnt[lbl]++;
    }
    __syncthreads();

    for (int i = t; i < C_NUM * DIMV; i += 256) atomicAdd(&g_sums[i], acc[i]);
    if (t < C_NUM) atomicAdd(&g_cnt[t], scnt[t]);
}

// ------------------- K3: normalize centroids (one block per class, tiny) -------------------
__global__ __launch_bounds__(256) void k_centroid() {
    int c = blockIdx.x;   // 0..15
    int t = threadIdx.x;  // 0..255
    __shared__ float sred[8];
    __shared__ float s_inv;

    float cf = (float)g_cnt[c];
    float mx = fmaxf(cf, 1.f);
    float c0 = g_sums[c * DIMV + t] / mx;
    float c1 = g_sums[c * DIMV + t + 256] / mx;

    float sq = c0 * c0 + c1 * c1;
    #pragma unroll
    for (int o = 16; o > 0; o >>= 1) sq += __shfl_down_sync(0xFFFFFFFFu, sq, o);
    if ((t & 31) == 0) sred[t >> 5] = sq;
    __syncthreads();
    if (t == 0) {
        float ns = 0.f;
        #pragma unroll
        for (int w = 0; w < 8; w++) ns += sred[w];
        s_inv = 1.f / fmaxf(sqrtf(ns), EPS_C);
        g_cntf[c] = cf;
    }
    __syncthreads();
    float inv = s_inv;
    float v0 = c0 * inv, v1 = c1 * inv;
    g_cnT[t * C_NUM + c]         = v0;   // transposed layout [d][c] for k_pass2
    g_cnT[(t + 256) * C_NUM + c] = v1;
    g_cnC[c * DIMV + t]          = v0;   // row-major [c][d] for k_pairs
    g_cnC[c * DIMV + t + 256]    = v1;
}

// ------------------- K3b: centroid pair analysis (single block, float4 smem dots) --------
__global__ __launch_bounds__(256) void k_pairs() {
    __shared__ __align__(16) float sc[C_NUM * PSTRIDE];   // ~33 KB padded [c][516]
    int t = threadIdx.x;                                  // 256 threads = 16x16 pairs
    for (int i = t; i < C_NUM * (DIMV / 4); i += 256) {
        int c = i >> 7, q = i & 127;
        *(float4*)&sc[c * PSTRIDE + q * 4] = *(const float4*)&g_cnC[c * DIMV + q * 4];
    }
    __syncthreads();

    int i = t >> 4, j = t & 15;
    const float* ri = &sc[i * PSTRIDE];
    const float* rj = &sc[j * PSTRIDE];
    float dot = 0.f;
    #pragma unroll 8
    for (int d = 0; d < DIMV; d += 4) {
        float4 a = *(const float4*)(ri + d);
        float4 b = *(const float4*)(rj + d);
        dot += a.x * b.x + a.y * b.y + a.z * b.z + a.w * b.w;
    }
    float pd = 1.f - dot;
    float ci = g_cntf[i], cj = g_cntf[j];
    float pm = (i < j && ci > 0.f && cj > 0.f && pd <= BETA_C) ? 1.f : 0.f;

    __shared__ float spm[256];
    __shared__ float sdeg[16];
    spm[t] = pm;
    g_pm[t] = pm;
    __syncthreads();
    if (t < 16) {
        float dg = 0.f;
        #pragma unroll
        for (int k = 0; k < 16; k++) dg += spm[t * 16 + k] + spm[k * 16 + t];
        sdeg[t] = dg;
        g_deg[t] = dg;
    }
    __syncthreads();
    if (t == 0) {
        float cnt_total = 0.f, np = 0.f;
        #pragma unroll
        for (int c = 0; c < 16; c++) cnt_total += sdeg[c] * g_cntf[c];
        for (int k = 0; k < 256; k++) np += spm[k];
        g_count = cnt_total;
        g_numpairs = np;
    }
}

// ------------------- K4: main pass — 4 samples/thread, shared centroids amortized --------
__global__ __launch_bounds__(P2_THREADS) void k_pass2(const float* __restrict__ emb,
                                                      const int* __restrict__ labels, int n) {
    __shared__ __align__(16) float s_c[DIMV * C_NUM];   // 32 KB [d][c]
    __shared__ float s_S[C_NUM * C_NUM];
    __shared__ float s_red[4];

    int t = threadIdx.x;
    for (int i = t; i < DIMV * C_NUM / 4; i += P2_THREADS)
        ((float4*)s_c)[i] = ((const float4*)g_cnT)[i];
    s_S[t] = 0.f; s_S[t + 128] = 0.f;
    __syncthreads();

    int row0 = blockIdx.x * P2_ROWS;
    int rows[P2_R];
    #pragma unroll
    for (int s = 0; s < P2_R; s++) rows[s] = row0 + t + s * P2_THREADS;

    unsigned long long acc2[P2_R][8];
    unsigned long long nrm2[P2_R];
    #pragma unroll
    for (int s = 0; s < P2_R; s++) {
        nrm2[s] = 0ull;
        #pragma unroll
        for (int c8 = 0; c8 < 8; c8++) acc2[s][c8] = 0ull;
    }

    const float4 zero4 = make_float4(0.f, 0.f, 0.f, 0.f);
    for (int d4 = 0; d4 < DIMV; d4 += 4) {
        float4 xv[P2_R];
        #pragma unroll
        for (int s = 0; s < P2_R; s++)
            xv[s] = (rows[s] < n) ? __ldg((const float4*)(emb + (size_t)rows[s] * DIMV + d4))
                                  : zero4;
        #pragma unroll
        for (int s = 0; s < P2_R; s++) {
            unsigned long long xy = pack2(xv[s].x, xv[s].y);
            unsigned long long zw = pack2(xv[s].z, xv[s].w);
            ffma2(nrm2[s], xy, xy);
            ffma2(nrm2[s], zw, zw);
        }
        const float* cb = &s_c[d4 * C_NUM];
        #pragma unroll
        for (int dd = 0; dd < 4; dd++) {
            // 16 classes for this dim: 4x LDS.128, each feeds all 4 samples
            ulonglong2 cva = *(const ulonglong2*)(cb + dd * C_NUM + 0);   // classes 0-3
            ulonglong2 cvb = *(const ulonglong2*)(cb + dd * C_NUM + 4);   // classes 4-7
            ulonglong2 cvc = *(const ulonglong2*)(cb + dd * C_NUM + 8);   // classes 8-11
            ulonglong2 cvd = *(const ulonglong2*)(cb + dd * C_NUM + 12);  // classes 12-15
            #pragma unroll
            for (int s = 0; s < P2_R; s++) {
                float xs = (&xv[s].x)[dd];
                unsigned long long xs2 = pack2(xs, xs);
                ffma2(acc2[s][0], xs2, cva.x);
                ffma2(acc2[s][1], xs2, cva.y);
                ffma2(acc2[s][2], xs2, cvb.x);
                ffma2(acc2[s][3], xs2, cvb.y);
                ffma2(acc2[s][4], xs2, cvc.x);
                ffma2(acc2[s][5], xs2, cvc.y);
                ffma2(acc2[s][6], xs2, cvd.x);
                ffma2(acc2[s][7], xs2, cvd.y);
            }
        }
    }

    // epilogue per sample: D[c] = 1 - cn[c]·xn ; fold into intra & S
    float intra_part = 0.f;
    #pragma unroll
    for (int s = 0; s < P2_R; s++) {
        if (rows[s] < n) {
            float accf[16];
            #pragma unroll
            for (int c8 = 0; c8 < 8; c8++)
                asm("mov.b64 {%0, %1}, %2;"
                    : "=f"(accf[2 * c8]), "=f"(accf[2 * c8 + 1]) : "l"(acc2[s][c8]));
            float nlo, nhi;
            asm("mov.b64 {%0, %1}, %2;" : "=f"(nlo), "=f"(nhi) : "l"(nrm2[s]));
            float nrm = nlo + nhi;

            int lbl = __ldg(&labels[rows[s]]);
            float inv = 1.f / fmaxf(sqrtf(nrm), EPS_C);
            float down = 0.f;
            #pragma unroll
            for (int c = 0; c < 16; c++) {
                float D = 1.f - accf[c] * inv;
                float v = BETA_C - D;
                if (v > 0.f) atomicAdd(&s_S[c * 16 + lbl], v);
                if (c == lbl) down = D;
            }
            intra_part += __ldg(&g_deg[lbl]) * fmaxf(down - ALPHA_C, 0.f);
        }
    }

    // block reduce intra, then flush
    #pragma unroll
    for (int o = 16; o > 0; o >>= 1)
        intra_part += __shfl_down_sync(0xFFFFFFFFu, intra_part, o);
    if ((t & 31) == 0) s_red[t >> 5] = intra_part;
    __syncthreads();   // also orders s_S shared atomics before the flush below
    if (t == 0)
        atomicAdd(&g_intra, s_red[0] + s_red[1] + s_red[2] + s_red[3]);
    atomicAdd(&g_S[t], s_S[t]);
    atomicAdd(&g_S[t + 128], s_S[t + 128]);
}

// ------------------- K5: final scalar -------------------
__global__ void k_final(float* __restrict__ out) {
    int t = threadIdx.x;   // 256
    __shared__ float sred[8];
    int i = t >> 4, j = t & 15;
    float v = g_pm[t] * (g_S[t] + g_S[j * 16 + i]);
    #pragma unroll
    for (int o = 16; o > 0; o >>= 1) v += __shfl_down_sync(0xFFFFFFFFu, v, o);
    if ((t & 31) == 0) sred[t >> 5] = v;
    __syncthreads();
    if (t == 0) {
        float inter = 0.f;
        #pragma unroll
        for (int w = 0; w < 8; w++) inter += sred[w];
        float denom = fmaxf(g_count, 1.f);
        out[0] = (g_numpairs > 0.f) ? (g_intra + inter) / denom : 0.f;
    }
}

// ------------------- launch -------------------
extern "C" void kernel_launch(void* const* d_in, const int* in_sizes, int n_in,
                              void* d_out, int out_size) {
    const float* emb    = (const float*)d_in[0];
    const int*   labels = (const int*)d_in[1];
    int n = in_sizes[1];   // number of samples (labels count)

    k_init<<<32, 256>>>();
    k_sums<<<K2_BLOCKS, 256>>>(emb, labels, n);
    k_centroid<<<C_NUM, 256>>>();
    k_pairs<<<1, 256>>>();
    int blocks = (n + P2_ROWS - 1) / P2_ROWS;
    k_pass2<<<blocks, P2_THREADS>>>(emb, labels, n);
    k_final<<<1, 256>>>((float*)d_out);
}